// round 7
// baseline (speedup 1.0000x reference)
#include <cuda_runtime.h>
#include <cstdint>

#define NUM_ANCHORS 145152
#define NUM_CH 85
#define IMG_SIZE 1536.0f
#define INV_IMG (1.0f / 1536.0f)
#define ROWS_PER_TILE 8
#define WARPS_PER_BLOCK 8
#define THREADS (WARPS_PER_BLOCK * 32)
#define DEPTH 4
#define NUM_TILES (NUM_ANCHORS / ROWS_PER_TILE)        // 18144
#define TILE_FLOATS (ROWS_PER_TILE * NUM_CH)           // 680
#define TILE_F4 (TILE_FLOATS / 4)                      // 170
#define BUF_FLOATS (DEPTH * TILE_FLOATS)               // per-warp ring buffer
#define SMEM_BYTES (WARPS_PER_BLOCK * BUF_FLOATS * 4)  // 87040 B

// d_out layout (fp32), reference tuple order, flattened:
//   [0 .. 4N)    bboxes     (N,4) = x0, y0, x1, y1
//   [4N .. 5N)   scores     (N,)
//   [5N .. 6N)   class_pred (N,)  (as float)
//   [6N .. 12N)  detections (N,6) = x0, y0, x1, y1, conf, cls

__device__ __forceinline__ unsigned smem_u32(const void* p) {
    unsigned a;
    asm("{ .reg .u64 t; cvta.to.shared.u64 t, %1; cvt.u32.u64 %0, t; }"
        : "=r"(a) : "l"(p));
    return a;
}

__device__ __forceinline__ void cp_async16(unsigned dst, const void* src) {
    asm volatile("cp.async.cg.shared.global [%0], [%1], 16;"
                 :: "r"(dst), "l"(src));
}

// Stage one 8-row tile (2720 B = 170 float4, contiguous) per warp.
// Caller commits the group.
__device__ __forceinline__ void issue_tile_load(unsigned dst0,
                                                const float* __restrict__ pred,
                                                int tile, int lane)
{
    const float4* src = (const float4*)(pred + (long long)tile * TILE_FLOATS);
    #pragma unroll
    for (int j = 0; j < TILE_F4 / 32; ++j)           // 5 full rounds
        cp_async16(dst0 + (lane + j * 32) * 16, src + lane + j * 32);
    if (lane < TILE_F4 - (TILE_F4 / 32) * 32)        // remainder: 10 lanes
        cp_async16(dst0 + (lane + (TILE_F4 / 32) * 32) * 16,
                   src + lane + (TILE_F4 / 32) * 32);
}

__device__ __forceinline__ void compute_tile(const float* __restrict__ s_base,
                                             float* __restrict__ out,
                                             int tile, int lane)
{
    const unsigned FULL = 0xffffffffu;
    const int row = lane >> 2;           // 0..7
    const int q   = lane & 3;            // quarter-lane within the row group
    const float* s = s_base + row * NUM_CH;   // all 4 group lanes: SAME row
    const int anchor = tile * ROWS_PER_TILE + row;

    // Header (broadcast reads — group lanes hit identical addresses).
    float cx  = s[0];
    float cy  = s[1];
    float w   = s[2];
    float h   = s[3];
    float obj = s[4];

    // Split class scan: lane q covers channels [20q .. 20q+19].
    const int base = 5 + 20 * q;
    float bv = s[base];
    int   bi = base - 5;
    #pragma unroll
    for (int k = 1; k < 20; ++k) {
        float v = s[base + k];
        if (v > bv) { bv = v; bi = base + k - 5; }
    }

    // Combine the four quarters (lowest index wins ties).
    #pragma unroll
    for (int off = 1; off <= 2; off <<= 1) {
        float ov = __shfl_xor_sync(FULL, bv, off);
        int   oi = __shfl_xor_sync(FULL, bi, off);
        if (ov > bv || (ov == bv && oi < bi)) { bv = ov; bi = oi; }
    }

    // /IMG_SIZE as reciprocal multiply (well inside the 1e-3 rel-err budget).
    float bx = cx * INV_IMG;
    float by = cy * INV_IMG;
    float bw = w  * INV_IMG;
    float bh = h  * INV_IMG;
    float x0 = bx - bw * 0.5f;
    float y0 = by - bh * 0.5f;
    float x1 = bx + bw * 0.5f;
    float y1 = by + bh * 0.5f;

    float conf  = bv;
    float clsf  = (float)bi;
    float score = obj * conf;

    float* out_sc  = out + (long long)NUM_ANCHORS * 4;
    float* out_cls = out + (long long)NUM_ANCHORS * 5;
    float* out_det = out + (long long)NUM_ANCHORS * 6;

    // Distribute writes across the 4 group lanes; every stream coalesced.
    if (q == 0) {
        ((float4*)out)[anchor] = make_float4(x0, y0, x1, y1);
    } else if (q == 1) {
        out_sc[anchor]  = score;
        out_cls[anchor] = clsf;
    } else {
        float2* det = (float2*)(out_det + (long long)anchor * 6);
        if (q == 2) {
            det[0] = make_float2(x0, y0);
            det[1] = make_float2(x1, y1);
        } else {
            det[2] = make_float2(conf, clsf);
        }
    }
}

__global__ __launch_bounds__(THREADS)
void yolo_decode_kernel(const float* __restrict__ pred,
                        float* __restrict__ out,
                        int n_warps_total)
{
    extern __shared__ float smem[];

    const int warp = threadIdx.x >> 5;
    const int lane = threadIdx.x & 31;
    const int wgid = blockIdx.x * WARPS_PER_BLOCK + warp;

    float* wbase = smem + warp * BUF_FLOATS;
    unsigned dsts[DEPTH];
    #pragma unroll
    for (int k = 0; k < DEPTH; ++k)
        dsts[k] = smem_u32(wbase + k * TILE_FLOATS);

    // ---- Prologue: put DEPTH-1 tile loads in flight ----
    #pragma unroll
    for (int k = 0; k < DEPTH - 1; ++k) {
        int t = wgid + k * n_warps_total;
        if (t < NUM_TILES)
            issue_tile_load(dsts[k], pred, t, lane);
        asm volatile("cp.async.commit_group;");
    }

    // ---- Steady state: always DEPTH-1 groups pending during compute ----
    int slot = 0;
    for (int t = wgid; t < NUM_TILES; t += n_warps_total) {
        int pf = t + (DEPTH - 1) * n_warps_total;
        int ps = slot + (DEPTH - 1);
        if (ps >= DEPTH) ps -= DEPTH;
        if (pf < NUM_TILES)
            issue_tile_load(dsts[ps], pred, pf, lane);
        asm volatile("cp.async.commit_group;");      // may be an empty group
        asm volatile("cp.async.wait_group %0;" :: "n"(DEPTH - 1));
        __syncwarp();

        compute_tile(wbase + slot * TILE_FLOATS, out, t, lane);

        if (++slot == DEPTH) slot = 0;
    }
}

extern "C" void kernel_launch(void* const* d_in, const int* in_sizes, int n_in,
                              void* d_out, int out_size)
{
    const float* pred = (const float*)d_in[0];
    // d_in[1] = score_threshold — unused by the reference computation.
    float* out = (float*)d_out;

    cudaFuncSetAttribute(yolo_decode_kernel,
                         cudaFuncAttributeMaxDynamicSharedMemorySize,
                         SMEM_BYTES);

    const int blocks = 296;                        // 2 per SM, persistent
    const int n_warps = blocks * WARPS_PER_BLOCK;  // 2368
    yolo_decode_kernel<<<blocks, THREADS, SMEM_BYTES>>>(pred, out, n_warps);
}